// round 2
// baseline (speedup 1.0000x reference)
#include <cuda_runtime.h>
#include <cstdint>

// Problem constants (match reference setup_inputs)
#define NN 100000
#define EE 1600000
#define DD 64

// Scratch aggregation buffer. Declared as float4 to guarantee 16B alignment
// for vectorized reductions and loads. (allocation-free: __device__ global)
__device__ float4 g_agg4[(size_t)NN * (DD / 4)];

// Flag: 1 if edge_index buffer is int64, 0 if int32 (JAX x64-disabled gives
// int32 even when jnp.int64 is requested).
__device__ int g_idx_is64;

// ---------------------------------------------------------------------------
// Phase 0: detect index width. Values are in [0, 100000) < 2^17, so if the
// buffer is int64 every odd 32-bit word is 0. If int32, odd words are random
// indices (P(zero) ~ 1e-5 each). One thread, 64 samples.
// ---------------------------------------------------------------------------
__global__ void detect_kernel(const unsigned int* __restrict__ ei_words) {
    int zeros = 0;
    #pragma unroll
    for (int i = 0; i < 64; i++) zeros += (ei_words[2 * i + 1] == 0u) ? 1 : 0;
    g_idx_is64 = (zeros >= 60) ? 1 : 0;
}

// ---------------------------------------------------------------------------
// Phase B: zero the aggregation buffer (float4 stores)
// ---------------------------------------------------------------------------
__global__ void __launch_bounds__(256) zero_agg_kernel() {
    int i = blockIdx.x * blockDim.x + threadIdx.x;
    const int total4 = NN * (DD / 4); // 1.6M float4
    if (i < total4) {
        g_agg4[i] = make_float4(0.f, 0.f, 0.f, 0.f);
    }
}

// ---------------------------------------------------------------------------
// Phase A: edge scatter. 16 threads per edge, each handles one float4 of the
// 64-wide feature row. msgs = x[src] * w, red.global.add.v4 into g_agg.
// ---------------------------------------------------------------------------
__global__ void __launch_bounds__(256) scatter_kernel(
    const float* __restrict__ x,
    const void* __restrict__ edge_index, // [2, E], int32 or int64
    const float* __restrict__ edge_attr)
{
    int gid = blockIdx.x * blockDim.x + threadIdx.x;
    int e = gid >> 4;        // edge id
    int q = gid & 15;        // float4 lane within the 64-wide row
    if (e >= EE) return;

    int src, dst;
    if (g_idx_is64) {
        const long long* ei = (const long long*)edge_index;
        src = (int)ei[e];
        dst = (int)ei[EE + e];
    } else {
        const int* ei = (const int*)edge_index;
        src = ei[e];
        dst = ei[EE + e];
    }
    float w = edge_attr[e];

    float4 v = reinterpret_cast<const float4*>(x)[(size_t)src * 16 + q];
    v.x *= w; v.y *= w; v.z *= w; v.w *= w;

    float* p = (float*)(g_agg4 + (size_t)dst * 16 + q);
    asm volatile("red.global.add.v4.f32 [%0], {%1, %2, %3, %4};"
                 :: "l"(p), "f"(v.x), "f"(v.y), "f"(v.z), "f"(v.w)
                 : "memory");
}

// ---------------------------------------------------------------------------
// Phase C: out = relu(agg @ W_rel^T + b_rel + x @ W_root^T)
// Block handles 16 nodes with 256 threads (16 threads/node, each thread does a
// float4 of the 64 outputs). Weights transposed into shared as [k][o] so the
// inner loop does float4 loads; node rows staged in shared with pad-68 rows.
// ---------------------------------------------------------------------------
__global__ void __launch_bounds__(256) output_kernel(
    const float* __restrict__ x,
    const float* __restrict__ W_rel,   // [64,64] row-major: W_rel[o][k]
    const float* __restrict__ b_rel,   // [64]
    const float* __restrict__ W_root,  // [64,64]
    float* __restrict__ out)
{
    __shared__ float Wr[DD * DD];      // transposed: Wr[k*64 + o]
    __shared__ float Wo[DD * DD];
    __shared__ float sa[16 * 68];      // agg rows, padded
    __shared__ float sx[16 * 68];      // x rows, padded

    int tid = threadIdx.x;

    // Transpose-load both weight matrices into shared (one-time cost).
    #pragma unroll
    for (int i = tid; i < DD * DD; i += 256) {
        int o = i >> 6;
        int k = i & 63;
        Wr[k * DD + o] = W_rel[i];
        Wo[k * DD + o] = W_root[i];
    }

    int nb = blockIdx.x * 16;          // first node of this block
    int t = tid >> 4;                  // node-in-block 0..15
    int j = tid & 15;                  // float4 index within 64-wide row

    // Stage agg and x rows (one float4 per thread per array).
    {
        float4 a4 = g_agg4[(size_t)(nb + t) * 16 + j];
        float4 r4 = reinterpret_cast<const float4*>(x)[(size_t)(nb + t) * 16 + j];
        reinterpret_cast<float4*>(sa + t * 68)[j] = a4;
        reinterpret_cast<float4*>(sx + t * 68)[j] = r4;
    }
    __syncthreads();

    float4 acc = reinterpret_cast<const float4*>(b_rel)[j];
    const float* ar = sa + t * 68;
    const float* xr = sx + t * 68;

    #pragma unroll
    for (int k = 0; k < DD; k++) {
        float a = ar[k];
        float r = xr[k];
        float4 wr = reinterpret_cast<const float4*>(Wr + k * DD)[j];
        float4 wo = reinterpret_cast<const float4*>(Wo + k * DD)[j];
        acc.x += a * wr.x + r * wo.x;
        acc.y += a * wr.y + r * wo.y;
        acc.z += a * wr.z + r * wo.z;
        acc.w += a * wr.w + r * wo.w;
    }

    acc.x = fmaxf(acc.x, 0.f);
    acc.y = fmaxf(acc.y, 0.f);
    acc.z = fmaxf(acc.z, 0.f);
    acc.w = fmaxf(acc.w, 0.f);

    reinterpret_cast<float4*>(out)[(size_t)(nb + t) * 16 + j] = acc;
}

// ---------------------------------------------------------------------------
// Launch: detect -> zero -> scatter -> output (capture stream, no syncs)
// Input order (metadata): x, edge_index, edge_attr, W_rel, b_rel, W_root
// ---------------------------------------------------------------------------
extern "C" void kernel_launch(void* const* d_in, const int* in_sizes, int n_in,
                              void* d_out, int out_size)
{
    const float* x     = (const float*)d_in[0];
    const void*  ei    = d_in[1];
    const float* ea    = (const float*)d_in[2];
    const float* Wrel  = (const float*)d_in[3];
    const float* brel  = (const float*)d_in[4];
    const float* Wroot = (const float*)d_in[5];
    float*       out   = (float*)d_out;

    // Phase 0: index width detection (1 thread; negligible)
    detect_kernel<<<1, 1>>>((const unsigned int*)ei);

    // Phase B: zero agg
    zero_agg_kernel<<<(NN * (DD / 4) + 255) / 256, 256>>>();

    // Phase A: scatter (E * 16 threads)
    {
        long long total = (long long)EE * 16;
        int blocks = (int)((total + 255) / 256);
        scatter_kernel<<<blocks, 256>>>(x, ei, ea);
    }

    // Phase C: fused dual-GEMV + bias + relu (16 nodes per block)
    output_kernel<<<NN / 16, 256>>>(x, Wrel, brel, Wroot, out);
}

// round 4
// speedup vs baseline: 1.9628x; 1.9628x over previous
#include <cuda_runtime.h>
#include <cstdint>

// Problem constants (match reference setup_inputs)
#define NN 100000
#define EE 1600000
#define DD 64

// Scratch aggregation buffer. float4 for guaranteed 16B alignment.
__device__ float4 g_agg4[(size_t)NN * (DD / 4)];

// 1 if edge_index buffer is int64, 0 if int32 (JAX x64-disabled downgrades).
__device__ int g_idx_is64;

// ---------------------------------------------------------------------------
// Phase 0: detect index width. Indices < 2^17, so int64 => odd words all 0.
// ---------------------------------------------------------------------------
__global__ void detect_kernel(const unsigned int* __restrict__ ei_words) {
    int zeros = 0;
    #pragma unroll
    for (int i = 0; i < 64; i++) zeros += (ei_words[2 * i + 1] == 0u) ? 1 : 0;
    g_idx_is64 = (zeros >= 60) ? 1 : 0;
}

// ---------------------------------------------------------------------------
// Phase B: zero the aggregation buffer
// ---------------------------------------------------------------------------
__global__ void __launch_bounds__(256) zero_agg_kernel() {
    int i = blockIdx.x * blockDim.x + threadIdx.x;
    const int total4 = NN * (DD / 4);
    if (i < total4) g_agg4[i] = make_float4(0.f, 0.f, 0.f, 0.f);
}

// ---------------------------------------------------------------------------
// Phase A: edge scatter. 16 threads/edge, red.global.add.v4 into g_agg.
// ---------------------------------------------------------------------------
__global__ void __launch_bounds__(256) scatter_kernel(
    const float* __restrict__ x,
    const void* __restrict__ edge_index, // [2, E], int32 or int64
    const float* __restrict__ edge_attr)
{
    int gid = blockIdx.x * blockDim.x + threadIdx.x;
    int e = gid >> 4;
    int q = gid & 15;
    if (e >= EE) return;

    int src, dst;
    if (g_idx_is64) {
        const long long* ei = (const long long*)edge_index;
        src = (int)ei[e];
        dst = (int)ei[EE + e];
    } else {
        const int* ei = (const int*)edge_index;
        src = ei[e];
        dst = ei[EE + e];
    }
    float w = edge_attr[e];

    float4 v = reinterpret_cast<const float4*>(x)[(size_t)src * 16 + q];
    v.x *= w; v.y *= w; v.z *= w; v.w *= w;

    float* p = (float*)(g_agg4 + (size_t)dst * 16 + q);
    asm volatile("red.global.add.v4.f32 [%0], {%1, %2, %3, %4};"
                 :: "l"(p), "f"(v.x), "f"(v.y), "f"(v.z), "f"(v.w)
                 : "memory");
}

// ---------------------------------------------------------------------------
// Phase C: out = relu(agg @ W_rel^T + b_rel + x @ W_root^T)
// Register-tiled: 256 threads/block, block covers 64 nodes.
//   t = tid>>4 selects a group of R=4 rows, j = tid&15 selects 4 outputs.
// Per k-iteration each thread loads wr/wo once and reuses across 4 rows
// (32 FMA per 64 B of LDS). Weights transposed in shared as [k][o].
// ---------------------------------------------------------------------------
#define ROWPAD 68
__global__ void __launch_bounds__(256, 3) output_kernel(
    const float* __restrict__ x,
    const float* __restrict__ W_rel,   // [64,64] row-major W[o][k]
    const float* __restrict__ b_rel,   // [64]
    const float* __restrict__ W_root,  // [64,64]
    float* __restrict__ out)
{
    __shared__ float Wr[DD * DD];      // Wr[k*64 + o]
    __shared__ float Wo[DD * DD];
    __shared__ float sa[64 * ROWPAD];  // 64 agg rows, padded
    __shared__ float sx[64 * ROWPAD];  // 64 x rows, padded

    int tid = threadIdx.x;
    int nb = blockIdx.x * 64;

    // Transpose-load both weight matrices into shared.
    #pragma unroll
    for (int i = tid; i < DD * DD; i += 256) {
        int o = i >> 6;
        int k = i & 63;
        Wr[k * DD + o] = W_rel[i];
        Wo[k * DD + o] = W_root[i];
    }

    // Stage 64 agg rows + 64 x rows (guard OOB rows in the tail block).
    #pragma unroll
    for (int it = 0; it < 4; it++) {
        int i = tid + it * 256;        // 0..1023 float4 slots
        int row = i >> 4;
        int q = i & 15;
        float4 a4 = make_float4(0.f, 0.f, 0.f, 0.f);
        float4 r4 = make_float4(0.f, 0.f, 0.f, 0.f);
        if (nb + row < NN) {
            a4 = g_agg4[(size_t)(nb + row) * 16 + q];
            r4 = reinterpret_cast<const float4*>(x)[(size_t)(nb + row) * 16 + q];
        }
        reinterpret_cast<float4*>(sa + row * ROWPAD)[q] = a4;
        reinterpret_cast<float4*>(sx + row * ROWPAD)[q] = r4;
    }
    __syncthreads();

    int t = tid >> 4;                  // row-group 0..15 (rows t*4..t*4+3)
    int j = tid & 15;                  // float4 output index

    float4 bias = reinterpret_cast<const float4*>(b_rel)[j];
    float4 acc0 = bias, acc1 = bias, acc2 = bias, acc3 = bias;

    const float* a0 = sa + (t * 4 + 0) * ROWPAD;
    const float* a1 = sa + (t * 4 + 1) * ROWPAD;
    const float* a2 = sa + (t * 4 + 2) * ROWPAD;
    const float* a3 = sa + (t * 4 + 3) * ROWPAD;
    const float* x0 = sx + (t * 4 + 0) * ROWPAD;
    const float* x1 = sx + (t * 4 + 1) * ROWPAD;
    const float* x2 = sx + (t * 4 + 2) * ROWPAD;
    const float* x3 = sx + (t * 4 + 3) * ROWPAD;

    #pragma unroll 8
    for (int k = 0; k < DD; k++) {
        float4 wr = reinterpret_cast<const float4*>(Wr + k * DD)[j];
        float4 wo = reinterpret_cast<const float4*>(Wo + k * DD)[j];
        float av0 = a0[k], av1 = a1[k], av2 = a2[k], av3 = a3[k];
        float xv0 = x0[k], xv1 = x1[k], xv2 = x2[k], xv3 = x3[k];

        acc0.x += av0 * wr.x + xv0 * wo.x;
        acc0.y += av0 * wr.y + xv0 * wo.y;
        acc0.z += av0 * wr.z + xv0 * wo.z;
        acc0.w += av0 * wr.w + xv0 * wo.w;

        acc1.x += av1 * wr.x + xv1 * wo.x;
        acc1.y += av1 * wr.y + xv1 * wo.y;
        acc1.z += av1 * wr.z + xv1 * wo.z;
        acc1.w += av1 * wr.w + xv1 * wo.w;

        acc2.x += av2 * wr.x + xv2 * wo.x;
        acc2.y += av2 * wr.y + xv2 * wo.y;
        acc2.z += av2 * wr.z + xv2 * wo.z;
        acc2.w += av2 * wr.w + xv2 * wo.w;

        acc3.x += av3 * wr.x + xv3 * wo.x;
        acc3.y += av3 * wr.y + xv3 * wo.y;
        acc3.z += av3 * wr.z + xv3 * wo.z;
        acc3.w += av3 * wr.w + xv3 * wo.w;
    }

    float4 accs[4] = {acc0, acc1, acc2, acc3};
    #pragma unroll
    for (int r = 0; r < 4; r++) {
        int nr = nb + t * 4 + r;
        if (nr < NN) {
            float4 v = accs[r];
            v.x = fmaxf(v.x, 0.f);
            v.y = fmaxf(v.y, 0.f);
            v.z = fmaxf(v.z, 0.f);
            v.w = fmaxf(v.w, 0.f);
            reinterpret_cast<float4*>(out)[(size_t)nr * 16 + j] = v;
        }
    }
}

// ---------------------------------------------------------------------------
// Launch: detect -> zero -> scatter -> output (capture stream, no syncs)
// Input order: x, edge_index, edge_attr, W_rel, b_rel, W_root
// ---------------------------------------------------------------------------
extern "C" void kernel_launch(void* const* d_in, const int* in_sizes, int n_in,
                              void* d_out, int out_size)
{
    const float* x     = (const float*)d_in[0];
    const void*  ei    = d_in[1];
    const float* ea    = (const float*)d_in[2];
    const float* Wrel  = (const float*)d_in[3];
    const float* brel  = (const float*)d_in[4];
    const float* Wroot = (const float*)d_in[5];
    float*       out   = (float*)d_out;

    detect_kernel<<<1, 1>>>((const unsigned int*)ei);

    zero_agg_kernel<<<(NN * (DD / 4) + 255) / 256, 256>>>();

    {
        long long total = (long long)EE * 16;
        int blocks = (int)((total + 255) / 256);
        scatter_kernel<<<blocks, 256>>>(x, ei, ea);
    }

    output_kernel<<<(NN + 63) / 64, 256>>>(x, Wrel, brel, Wroot, out);
}